// round 13
// baseline (speedup 1.0000x reference)
#include <cuda_runtime.h>

// LensCrack: out = clip(where(crack_mask, 0.05, x), 0, 1)
// x: [16, 3, 1024, 1024] fp32, endpoints: [16, 8, 4] int32 rows (y0,x0,y1,x1)

#define CRACK_VAL 0.05f

static constexpr int Bc = 16;
static constexpr int Cc = 3;
static constexpr int Hc = 1024;
static constexpr int Wc = 1024;
static constexpr int Kc = 8;          // cracks per batch
static constexpr int HW = Hc * Wc;    // 1 << 20

// ---------------------------------------------------------------------------
// Kernel 1: HBM-bound clipped copy. float4 vectorized, one vec per thread.
// 50,331,648 elems = 12,582,912 float4 -> 49152 blocks x 256 threads.
// ---------------------------------------------------------------------------
__global__ void __launch_bounds__(256) lenscrack_clip_copy(
    const float4* __restrict__ x, float4* __restrict__ out, int n4)
{
    int i = blockIdx.x * blockDim.x + threadIdx.x;
    if (i < n4) {
        float4 v = x[i];
        v.x = fminf(fmaxf(v.x, 0.0f), 1.0f);
        v.y = fminf(fmaxf(v.y, 0.0f), 1.0f);
        v.z = fminf(fmaxf(v.z, 0.0f), 1.0f);
        v.w = fminf(fmaxf(v.w, 0.0f), 1.0f);
        out[i] = v;
    }
}

// ---------------------------------------------------------------------------
// Kernel 2: parallel crack rasterization via closed-form Bresenham.
//
// Reference recurrence (per step t, record THEN update):
//   record (cx,cy) valid if t <= nsteps
//   e2 = 2*err
//   if (e2 > -dy) { err -= dy; cx += sx; }   // strict >
//   if (e2 <  dx) { err += dx; cy += sy; }   // strict <
// with err0 = dx - dy, nsteps = max(dx,dy).
//
// Closed form (derived from the recurrence, tie-breaks preserved):
//   dx >= dy: cx(t) = x0 + sx*t
//             cy(t) = y0 + sy * max(0, ceil((2*dy*t - dx) / (2*dx)))
//   dy >  dx: cy(t) = y0 + sy*t
//             cx(t) = x0 + sx * max(0, ceil((2*dx*t - dy) / (2*dy)))
//
// One block per line (128 blocks), one thread per step t in [0, 1023].
// Writing CRACK_VAL is idempotent, so duplicate pixels across lines are fine.
// ---------------------------------------------------------------------------
__global__ void __launch_bounds__(1024) lenscrack_scatter(
    const int* __restrict__ ep, float* __restrict__ out)
{
    const int line = blockIdx.x;          // 0 .. B*K-1
    const int b    = line >> 3;           // K = 8
    const int y0 = ep[line * 4 + 0];
    const int x0 = ep[line * 4 + 1];
    const int y1 = ep[line * 4 + 2];
    const int x1 = ep[line * 4 + 3];

    const int dx = abs(x1 - x0);
    const int dy = abs(y1 - y0);
    const int sx = (x0 < x1) ? 1 : -1;
    const int sy = (y0 < y1) ? 1 : -1;
    const int nsteps = max(dx, dy);

    const int t = threadIdx.x;
    if (t > nsteps) return;

    int cx, cy;
    if (dx >= dy) {
        cx = x0 + sx * t;
        int num = 2 * dy * t - dx;
        // num > 0 implies dx >= 1 (if dx == 0 then dy == 0 and num == 0)
        int n = (num <= 0) ? 0 : (num + 2 * dx - 1) / (2 * dx);
        cy = y0 + sy * n;
    } else {
        cy = y0 + sy * t;
        int num = 2 * dx * t - dy;
        int m = (num <= 0) ? 0 : (num + 2 * dy - 1) / (2 * dy);
        cx = x0 + sx * m;
    }

    if ((unsigned)cx < (unsigned)Wc && (unsigned)cy < (unsigned)Hc) {
        float* p = out + (long long)b * Cc * HW + cy * Wc + cx;
        p[0]        = CRACK_VAL;
        p[HW]       = CRACK_VAL;
        p[2 * HW]   = CRACK_VAL;
    }
}

// ---------------------------------------------------------------------------
extern "C" void kernel_launch(void* const* d_in, const int* in_sizes, int n_in,
                              void* d_out, int out_size)
{
    const float* x  = (const float*)d_in[0];   // 16*3*1024*1024 fp32
    const int*   ep = (const int*)d_in[1];     // 16*8*4 int32
    float* out = (float*)d_out;

    const int n  = in_sizes[0];                // 50,331,648
    const int n4 = n >> 2;                     // 12,582,912
    const int threads = 256;
    const int blocks = (n4 + threads - 1) / threads;

    lenscrack_clip_copy<<<blocks, threads>>>(
        (const float4*)x, (float4*)out, n4);

    lenscrack_scatter<<<Bc * Kc, Hc>>>(ep, out);
}

// round 14
// speedup vs baseline: 1.0675x; 1.0675x over previous
#include <cuda_runtime.h>

// LensCrack: out = clip(where(crack_mask, 0.05, x), 0, 1)
// x: [16, 3, 1024, 1024] fp32, endpoints: [16, 8, 4] int32 rows (y0,x0,y1,x1)

#define CRACK_VAL 0.05f

static constexpr int Bc = 16;
static constexpr int Cc = 3;
static constexpr int Hc = 1024;
static constexpr int Wc = 1024;
static constexpr int Kc = 8;          // cracks per batch
static constexpr int HW = Hc * Wc;    // 1 << 20

// ---------------------------------------------------------------------------
// Kernel 1: HBM-bound clipped copy.
// 2x float4 per thread, loads front-batched (MLP=2), streaming cache hints
// (evict-first: the 2x201MB stream would otherwise thrash the 126MB L2).
// 512 threads/block, 1024 float4 per block -> 12288 blocks exactly.
// Triggers programmatic launch completion for the dependent scatter kernel.
// ---------------------------------------------------------------------------
__global__ void __launch_bounds__(512) lenscrack_clip_copy(
    const float4* __restrict__ x, float4* __restrict__ out)
{
    const int base = blockIdx.x * 1024 + threadIdx.x;

    // front-batched independent loads
    float4 a = __ldcs(&x[base]);
    float4 b = __ldcs(&x[base + 512]);

    a.x = __saturatef(a.x); a.y = __saturatef(a.y);
    a.z = __saturatef(a.z); a.w = __saturatef(a.w);
    b.x = __saturatef(b.x); b.y = __saturatef(b.y);
    b.z = __saturatef(b.z); b.w = __saturatef(b.w);

    __stcs(&out[base],       a);
    __stcs(&out[base + 512], b);

#if __CUDA_ARCH__ >= 900
    cudaTriggerProgrammaticLaunchCompletion();
#endif
}

// ---------------------------------------------------------------------------
// Kernel 2: parallel crack rasterization via closed-form Bresenham.
//
// Reference recurrence (record THEN update, err0 = dx-dy, nsteps = max(dx,dy)):
//   if (2*err > -dy) { err -= dy; cx += sx; }   // strict >
//   if (2*err <  dx) { err += dx; cy += sy; }   // strict <
// Closed form (tie-breaks preserved, verified against recurrence):
//   dx >= dy: cx(t) = x0 + sx*t
//             cy(t) = y0 + sy * max(0, ceil((2*dy*t - dx) / (2*dx)))
//   dy >  dx: symmetric.
//
// Grid: 512 blocks x 256 threads — 4 blocks per line, quarter-line each,
// spread across all SMs. PDL: all compute happens BEFORE
// cudaGridDependencySynchronize(); only the 3 stores come after, so the
// kernel's prelude overlaps the copy kernel's tail.
// ---------------------------------------------------------------------------
__global__ void __launch_bounds__(256) lenscrack_scatter(
    const int* __restrict__ ep, float* __restrict__ out)
{
    const int line = blockIdx.x >> 2;                      // 0 .. B*K-1
    const int t    = ((blockIdx.x & 3) << 8) + threadIdx.x; // 0 .. 1023
    const int b    = line >> 3;                            // K = 8

    const int y0 = ep[line * 4 + 0];
    const int x0 = ep[line * 4 + 1];
    const int y1 = ep[line * 4 + 2];
    const int x1 = ep[line * 4 + 3];

    const int dx = abs(x1 - x0);
    const int dy = abs(y1 - y0);
    const int sx = (x0 < x1) ? 1 : -1;
    const int sy = (y0 < y1) ? 1 : -1;
    const int nsteps = max(dx, dy);

    int cx, cy;
    if (dx >= dy) {
        cx = x0 + sx * t;
        int num = 2 * dy * t - dx;
        int n = (num <= 0) ? 0 : (num + 2 * dx - 1) / (2 * dx);
        cy = y0 + sy * n;
    } else {
        cy = y0 + sy * t;
        int num = 2 * dx * t - dy;
        int m = (num <= 0) ? 0 : (num + 2 * dy - 1) / (2 * dy);
        cx = x0 + sx * m;
    }

    const bool ok = (t <= nsteps) &&
                    ((unsigned)cx < (unsigned)Wc) &&
                    ((unsigned)cy < (unsigned)Hc);
    float* p = out + (long long)b * Cc * HW + cy * Wc + cx;

#if __CUDA_ARCH__ >= 900
    cudaGridDependencySynchronize();   // wait for copy's writes to be visible
#endif

    if (ok) {
        p[0]      = CRACK_VAL;
        p[HW]     = CRACK_VAL;
        p[2 * HW] = CRACK_VAL;
    }
}

// ---------------------------------------------------------------------------
extern "C" void kernel_launch(void* const* d_in, const int* in_sizes, int n_in,
                              void* d_out, int out_size)
{
    const float* x  = (const float*)d_in[0];   // 16*3*1024*1024 fp32
    const int*   ep = (const int*)d_in[1];     // 16*8*4 int32
    float* out = (float*)d_out;

    const int n  = in_sizes[0];                // 50,331,648
    const int n4 = n >> 2;                     // 12,582,912
    const int blocks = n4 / 1024;              // 12288 (exact)

    lenscrack_clip_copy<<<blocks, 512>>>((const float4*)x, (float4*)out);

    // Dependent launch: scatter's prelude overlaps the copy tail (PDL).
    cudaLaunchConfig_t cfg = {};
    cfg.gridDim  = dim3(Bc * Kc * 4, 1, 1);    // 512 blocks
    cfg.blockDim = dim3(256, 1, 1);
    cudaLaunchAttribute attrs[1];
    attrs[0].id = cudaLaunchAttributeProgrammaticStreamSerialization;
    attrs[0].val.programmaticStreamSerializationAllowed = 1;
    cfg.attrs = attrs;
    cfg.numAttrs = 1;
    cudaLaunchKernelEx(&cfg, lenscrack_scatter, ep, out);
}